// round 15
// baseline (speedup 1.0000x reference)
#include <cuda_runtime.h>

// NURBS surface eval: DEG=3, N_CP=32x32, N_EVAL=2,000,000.
// Clamped-uniform knots: knot(i) = clamp(i-3,0,29)/29, span = floor(u*29)+3.
// Output: d_out[0..4N) = points (x,y,z,1); d_out[4N..8N) = normals (nx,ny,nz,0).
//
// R15 = R13 basis (closed-form reciprocals, no divides) + packed-xy FFMA2
// contraction with data BORN packed (fixing R6's pack-mov overhead):
//  * smem split: xy table = float2, 16 bank-columns (128 KB): bank-pair of
//    entry cell*16+col is 2*col, cell-INDEPENDENT -> LDS.64 provably
//    conflict-free. z table = float, 16 columns (64 KB), ~2 transactions.
//    Total 192 KB (B200 has 227 KB/SM; occupancy already 1 block).
//  * inner loop: 2x fma.rn.f32x2 (xy) + 2 scalar z FMA = 4 instr/cell vs 6.
//  * derivative x3 scale dropped: uniform on both partials -> cancels in the
//    normalized cross product.
// Partition of unity => homogeneous w == 1 (no divide).

#define NCP 32
#define NTHREADS 1024
#define NBLOCKS 148
#define XY_ENTRIES (NCP * NCP * 16)                  // 16384 float2 = 128 KB
#define Z_ENTRIES  (NCP * NCP * 16)                  // 16384 float  =  64 KB
#define TAB_BYTES  (XY_ENTRIES * 8 + Z_ENTRIES * 4)  // 196608 B

typedef unsigned long long f2;   // packed (x, y)

__device__ __forceinline__ f2 bc2(float x) {
    f2 r; asm("mov.b64 %0, {%1, %1};" : "=l"(r) : "r"(__float_as_uint(x)));
    return r;
}
__device__ __forceinline__ void unpack2(f2 v, float& lo, float& hi) {
    unsigned a, b;
    asm("mov.b64 {%0, %1}, %2;" : "=r"(a), "=r"(b) : "l"(v));
    lo = __uint_as_float(a); hi = __uint_as_float(b);
}
__device__ __forceinline__ f2 fma2(f2 a, f2 b, f2 c) {
    f2 r; asm("fma.rn.f32x2 %0, %1, %2, %3;" : "=l"(r) : "l"(a), "l"(b), "l"(c));
    return r;
}

// Cox-de Boor p=3 (clamped-uniform), closed-form reciprocals, no divides.
// Outputs N[0..3] and UNscaled derivative ingredients D[0..3] (d/du / (3*29)
// effectively; uniform positive scale cancels in the normalized cross).
__device__ __forceinline__ void basis3(float u, int se,
                                       float* __restrict__ Nb, float* __restrict__ Db) {
    const float C  = 1.0f / 29.0f;
    const float R1 = 29.0f, R2 = 14.5f, R3 = 29.0f / 3.0f;
    float sef = (float)se;

    float k0  = sef * C;
    float k1  = fmaf(1.0f, C, k0);                    // never clamps
    float km1 = fmaxf(k0 - C, 0.0f);
    float km2 = fmaxf(fmaf(-2.0f, C, k0), 0.0f);
    float k2  = fminf(fmaf(2.0f, C, k0), 1.0f);
    float k3  = fminf(fmaf(3.0f, C, k0), 1.0f);

    float l1 = u - k0, l2 = u - km1, l3 = u - km2;
    float r1 = k1 - u, r2 = k2 - u, r3 = k3 - u;

    bool se0 = (se == 0), se1 = (se == 1), se27 = (se == 27), se28 = (se == 28);
    float i20 = se0  ? R1 : R2;
    float i21 = se28 ? R1 : R2;
    float i30 = se0  ? R1 : (se1 ? R2 : R3);
    float i31 = (se0 || se28) ? R2 : R3;
    float i32 = se28 ? R1 : (se27 ? R2 : R3);

    float n01 = r1 * R1;
    float n11 = l1 * R1;
    float q20 = n01 * i20;
    float n02 = r1 * q20;
    float s2  = l2 * q20;
    float q21 = n11 * i21;
    float n12 = fmaf(r2, q21, s2);
    float n22 = l1 * q21;
    float t0 = n02 * i30;
    Nb[0] = r1 * t0;
    float s3 = l3 * t0;
    float t1 = n12 * i31;
    Nb[1] = fmaf(r2, t1, s3);
    s3 = l2 * t1;
    float t2 = n22 * i32;
    Nb[2] = fmaf(r3, t2, s3);
    Nb[3] = l1 * t2;

    Db[0] = -t0;           // x3 scale dropped (cancels after normalization)
    Db[1] = t0 - t1;
    Db[2] = t1 - t2;
    Db[3] = t2;
}

extern "C" __global__ void __launch_bounds__(NTHREADS, 1)
nurbs_surface_kernel(const float2* __restrict__ ep,
                     const float*  __restrict__ cp,
                     float4* __restrict__ out,
                     int n)
{
    extern __shared__ char smem[];
    f2*    __restrict__ xyt = (f2*)smem;                        // packed (x,y)
    float* __restrict__ zt  = (float*)(smem + XY_ENTRIES * 8);  // z

    const int tid    = threadIdx.x;
    const int lane16 = tid & 15;

    // Fill: 16x replicated, bank-column striped (linear e -> conflict-free STS)
    for (int e = tid; e < XY_ENTRIES; e += NTHREADS) {
        int cell = e >> 4;
        float2 v = make_float2(cp[3 * cell + 0], cp[3 * cell + 1]);
        ((float2*)xyt)[e] = v;
        zt[e] = cp[3 * cell + 2];
    }
    __syncthreads();

    float4* __restrict__ outn = out + n;

    for (int idx = blockIdx.x * NTHREADS + tid; idx < n; idx += NBLOCKS * NTHREADS) {
        float2 uv = ep[idx];

        int se = (int)floorf(uv.x * 29.0f);
        se = se < 0 ? 0 : (se > 28 ? 28 : se);
        int sn = (int)floorf(uv.y * 29.0f);
        sn = sn < 0 ? 0 : (sn > 28 ? 28 : sn);

        float Nu[4], Du[4], Nv[4], Dv[4];
        basis3(uv.x, se, Nu, Du);
        basis3(uv.y, sn, Nv, Dv);

        // broadcast v-weights into packed form (reused over 4 rows)
        f2 Nv2[4], Dv2[4];
#pragma unroll
        for (int s = 0; s < 4; ++s) { Nv2[s] = bc2(Nv[s]); Dv2[s] = bc2(Dv[s]); }

        // conflict-free gather base: lane-private bank column
        const int base = (se * NCP + sn) * 16 + lane16;

        f2 pxy = 0ull, exy = 0ull, fxy = 0ull;
        float pz = 0.f, ez = 0.f, fz = 0.f;
#pragma unroll
        for (int r = 0; r < 4; ++r) {
            f2 axy = 0ull, bxy = 0ull;
            float az = 0.f, bz = 0.f;
            const int rowb = base + r * (NCP * 16);
#pragma unroll
            for (int s = 0; s < 4; ++s) {
                f2    gxy = xyt[rowb + s * 16];
                float gz  = zt [rowb + s * 16];
                axy = fma2(Nv2[s], gxy, axy);
                bxy = fma2(Dv2[s], gxy, bxy);
                az  = fmaf(Nv[s], gz, az);
                bz  = fmaf(Dv[s], gz, bz);
            }
            f2 nu2 = bc2(Nu[r]), du2 = bc2(Du[r]);
            pxy = fma2(nu2, axy, pxy);
            exy = fma2(du2, axy, exy);
            fxy = fma2(nu2, bxy, fxy);
            pz = fmaf(Nu[r], az, pz);
            ez = fmaf(Du[r], az, ez);
            fz = fmaf(Nu[r], bz, fz);
        }

        float px, py, ex, ey, fx, fy;
        unpack2(pxy, px, py);
        unpack2(exy, ex, ey);
        unpack2(fxy, fx, fy);

        // normal = normalize(cross(d_e, d_n)); uniform scales cancel
        float cx = ey * fz - ez * fy;
        float cy = ez * fx - ex * fz;
        float cz = ex * fy - ey * fx;
        float il = rsqrtf(cx * cx + cy * cy + cz * cz);

        out[idx]  = make_float4(px, py, pz, 1.0f);
        outn[idx] = make_float4(cx * il, cy * il, cz * il, 0.0f);
    }
}

extern "C" void kernel_launch(void* const* d_in, const int* in_sizes, int n_in,
                              void* d_out, int out_size)
{
    const float2* ep = (const float2*)d_in[0];   // evaluation_points (N,2)
    const float*  cp = (const float*)d_in[1];    // control_points (32,32,3)
    int n = in_sizes[0] / 2;
    float4* out = (float4*)d_out;

    cudaFuncSetAttribute(nurbs_surface_kernel,
                         cudaFuncAttributeMaxDynamicSharedMemorySize, TAB_BYTES);

    nurbs_surface_kernel<<<NBLOCKS, NTHREADS, TAB_BYTES>>>(ep, cp, out, n);
}

// round 16
// speedup vs baseline: 1.0155x; 1.0155x over previous
#include <cuda_runtime.h>

// NURBS surface eval: DEG=3, N_CP=32x32, N_EVAL=2,000,000.
// Clamped-uniform knots: knot(i) = clamp(i-3,0,29)/29, span = floor(u*29)+3.
// Output: d_out[0..4N) = points (x,y,z,1); d_out[4N..8N) = normals (nx,ny,nz,0).
//
// R16 = R13 champion (persistent 148x1024, 8x bank-column-replicated float4
// smem table -> zero LDS conflicts, closed-form-reciprocal Cox-de Boor basis,
// separable contraction, w==1) + ONE change:
//  * uv double-buffered across grid-stride iterations: the loop-head LDG
//    (DRAM, ~400-600cyc under load) is issued one iteration early, removing
//    the dependent-load stall at the top of every iteration.

#define NCP 32
#define NTHREADS 1024
#define NBLOCKS 148
#define TAB_BYTES (NCP * NCP * 8 * 16)   // 128 KB

// Cox-de Boor p=3 (clamped-uniform knots), fully unrolled, no divides/MUFU.
// se in [0,28]; outputs basis N[0..3] and derivatives D[0..3] (already *p).
__device__ __forceinline__ void basis3(float u, int se,
                                       float* __restrict__ Nb, float* __restrict__ Db) {
    const float C  = 1.0f / 29.0f;
    const float R1 = 29.0f, R2 = 14.5f, R3 = 29.0f / 3.0f;
    float sef = (float)se;

    // local knots; only 4 can actually clamp
    float k0  = sef * C;
    float k1  = fmaf(1.0f, C, k0);                    // (se+1)/29, never clamps
    float km1 = fmaxf(k0 - C, 0.0f);
    float km2 = fmaxf(fmaf(-2.0f, C, k0), 0.0f);
    float k2  = fminf(fmaf(2.0f, C, k0), 1.0f);
    float k3  = fminf(fmaf(3.0f, C, k0), 1.0f);

    float l1 = u - k0, l2 = u - km1, l3 = u - km2;
    float r1 = k1 - u, r2 = k2 - u, r3 = k3 - u;

    // reciprocals of the integer knot-span widths (in units of 1/29):
    bool se0 = (se == 0), se1 = (se == 1), se27 = (se == 27), se28 = (se == 28);
    float i20 = se0  ? R1 : R2;                 // j=2, r=0
    float i21 = se28 ? R1 : R2;                 // j=2, r=1
    float i30 = se0  ? R1 : (se1 ? R2 : R3);    // j=3, r=0
    float i31 = (se0 || se28) ? R2 : R3;        // j=3, r=1
    float i32 = se28 ? R1 : (se27 ? R2 : R3);   // j=3, r=2

    // j=1 (den always 1/29)
    float n01 = r1 * R1;
    float n11 = l1 * R1;
    // j=2
    float q20 = n01 * i20;
    float n02 = r1 * q20;
    float s2  = l2 * q20;
    float q21 = n11 * i21;
    float n12 = fmaf(r2, q21, s2);
    float n22 = l1 * q21;
    // j=3 (quotients are exactly the derivative t_r values)
    float t0 = n02 * i30;
    Nb[0] = r1 * t0;
    float s3 = l3 * t0;
    float t1 = n12 * i31;
    Nb[1] = fmaf(r2, t1, s3);
    s3 = l2 * t1;
    float t2 = n22 * i32;
    Nb[2] = fmaf(r3, t2, s3);
    Nb[3] = l1 * t2;

    Db[0] = -3.0f * t0;
    Db[1] = 3.0f * (t0 - t1);
    Db[2] = 3.0f * (t1 - t2);
    Db[3] = 3.0f * t2;
}

extern "C" __global__ void __launch_bounds__(NTHREADS, 1)
nurbs_surface_kernel(const float2* __restrict__ ep,
                     const float*  __restrict__ cp,
                     float4* __restrict__ out,
                     int n)
{
    extern __shared__ float4 tab[];   // [1024 cells][8 bank-columns]
    const int tid   = threadIdx.x;
    const int lane8 = tid & 7;

#pragma unroll
    for (int i = 0; i < 8; ++i) {
        int e = i * NTHREADS + tid;
        int cell = e >> 3;
        tab[e] = make_float4(cp[3 * cell + 0], cp[3 * cell + 1], cp[3 * cell + 2], 1.0f);
    }
    __syncthreads();

    float4* __restrict__ outn = out + n;
    const int stride = NBLOCKS * NTHREADS;
    int idx = blockIdx.x * NTHREADS + tid;
    if (idx >= n) return;

    float2 uv = ep[idx];                     // prologue load

    while (true) {
        float u = uv.x, v = uv.y;

        int se = (int)floorf(u * 29.0f);
        se = se < 0 ? 0 : (se > 28 ? 28 : se);
        int sn = (int)floorf(v * 29.0f);
        sn = sn < 0 ? 0 : (sn > 28 ? 28 : sn);

        // prefetch next iteration's uv: LDG issued here, consumed next iter
        int nidx = idx + stride;
        bool has_next = nidx < n;
        if (has_next) uv = ep[nidx];

        float Nu[4], Du[4], Nv[4], Dv[4];
        basis3(u, se, Nu, Du);
        basis3(v, sn, Nv, Dv);

        // Conflict-free gather base: this lane's private bank column.
        const float4* __restrict__ p = tab + ((se * NCP + sn) * 8 + lane8);

        float px=0.f,py=0.f,pz=0.f;   // surface point (homogeneous w == 1)
        float ex=0.f,ey=0.f,ez=0.f;   // d/du
        float fx=0.f,fy=0.f,fz=0.f;   // d/dv
#pragma unroll
        for (int r = 0; r < 4; ++r) {
            float ax=0.f, ay=0.f, az=0.f;
            float bx=0.f, by=0.f, bz=0.f;
#pragma unroll
            for (int s = 0; s < 4; ++s) {
                float4 g = p[(r * NCP + s) * 8];
                float nv = Nv[s], dv = Dv[s];
                ax = fmaf(nv, g.x, ax); ay = fmaf(nv, g.y, ay); az = fmaf(nv, g.z, az);
                bx = fmaf(dv, g.x, bx); by = fmaf(dv, g.y, by); bz = fmaf(dv, g.z, bz);
            }
            float nu = Nu[r], du = Du[r];
            px = fmaf(nu, ax, px); py = fmaf(nu, ay, py); pz = fmaf(nu, az, pz);
            ex = fmaf(du, ax, ex); ey = fmaf(du, ay, ey); ez = fmaf(du, az, ez);
            fx = fmaf(nu, bx, fx); fy = fmaf(nu, by, fy); fz = fmaf(nu, bz, fz);
        }

        // normal = normalize(cross(d_e, d_n))
        float cx = ey * fz - ez * fy;
        float cy = ez * fx - ex * fz;
        float cz = ex * fy - ey * fx;
        float il = rsqrtf(cx * cx + cy * cy + cz * cz);

        out[idx]  = make_float4(px, py, pz, 1.0f);
        outn[idx] = make_float4(cx * il, cy * il, cz * il, 0.0f);

        if (!has_next) break;
        idx = nidx;
    }
}

extern "C" void kernel_launch(void* const* d_in, const int* in_sizes, int n_in,
                              void* d_out, int out_size)
{
    const float2* ep = (const float2*)d_in[0];   // evaluation_points (N,2)
    const float*  cp = (const float*)d_in[1];    // control_points (32,32,3)
    int n = in_sizes[0] / 2;
    float4* out = (float4*)d_out;

    cudaFuncSetAttribute(nurbs_surface_kernel,
                         cudaFuncAttributeMaxDynamicSharedMemorySize, TAB_BYTES);

    nurbs_surface_kernel<<<NBLOCKS, NTHREADS, TAB_BYTES>>>(ep, cp, out, n);
}

// round 17
// speedup vs baseline: 1.0256x; 1.0100x over previous
#include <cuda_runtime.h>

// NURBS surface eval: DEG=3, N_CP=32x32, N_EVAL=2,000,000.
// Clamped-uniform knots: knot(i) = clamp(i-3,0,29)/29, span = floor(u*29)+3.
// Output: d_out[0..4N) = points (x,y,z,1); d_out[4N..8N) = normals (nx,ny,nz,0).
//
// R17 = R13 champion (persistent 148x1024, 8x bank-column-replicated float4
// smem table -> zero LDS conflicts, closed-form-reciprocal Cox-de Boor,
// separable contraction, w==1) minus the last removable instructions:
//  * span = (int)(u*29): u in [0,1) guaranteed -> u*29 in [0,29) in fp32
//    (worst case (1-2^-24)*29 rounds to 28.999998), so trunc-cast alone gives
//    se in [0,28]: no floorf insn, no clamps.
//  * derivative x3 scale dropped: uniform positive on both partials ->
//    cancels in the normalized cross product (validated in R15).
//  * incremental output pointers (uniform-register-friendly).

#define NCP 32
#define NTHREADS 1024
#define NBLOCKS 148
#define TAB_BYTES (NCP * NCP * 8 * 16)   // 128 KB

// Cox-de Boor p=3 (clamped-uniform knots), fully unrolled, no divides/MUFU.
// se in [0,28]; outputs basis N[0..3] and UNSCALED derivative weights D[0..3]
// (true derivative = 3*29*D; uniform scale cancels after normalization).
__device__ __forceinline__ void basis3(float u, int se,
                                       float* __restrict__ Nb, float* __restrict__ Db) {
    const float C  = 1.0f / 29.0f;
    const float R1 = 29.0f, R2 = 14.5f, R3 = 29.0f / 3.0f;
    float sef = (float)se;

    // local knots; only 4 can actually clamp
    float k0  = sef * C;
    float k1  = fmaf(1.0f, C, k0);                    // (se+1)/29, never clamps
    float km1 = fmaxf(k0 - C, 0.0f);
    float km2 = fmaxf(fmaf(-2.0f, C, k0), 0.0f);
    float k2  = fminf(fmaf(2.0f, C, k0), 1.0f);
    float k3  = fminf(fmaf(3.0f, C, k0), 1.0f);

    float l1 = u - k0, l2 = u - km1, l3 = u - km2;
    float r1 = k1 - u, r2 = k2 - u, r3 = k3 - u;

    // reciprocals of the integer knot-span widths (in units of 1/29):
    bool se0 = (se == 0), se1 = (se == 1), se27 = (se == 27), se28 = (se == 28);
    float i20 = se0  ? R1 : R2;                 // j=2, r=0
    float i21 = se28 ? R1 : R2;                 // j=2, r=1
    float i30 = se0  ? R1 : (se1 ? R2 : R3);    // j=3, r=0
    float i31 = (se0 || se28) ? R2 : R3;        // j=3, r=1
    float i32 = se28 ? R1 : (se27 ? R2 : R3);   // j=3, r=2

    // j=1 (den always 1/29)
    float n01 = r1 * R1;
    float n11 = l1 * R1;
    // j=2
    float q20 = n01 * i20;
    float n02 = r1 * q20;
    float s2  = l2 * q20;
    float q21 = n11 * i21;
    float n12 = fmaf(r2, q21, s2);
    float n22 = l1 * q21;
    // j=3 (quotients are exactly the derivative ingredients t_r)
    float t0 = n02 * i30;
    Nb[0] = r1 * t0;
    float s3 = l3 * t0;
    float t1 = n12 * i31;
    Nb[1] = fmaf(r2, t1, s3);
    s3 = l2 * t1;
    float t2 = n22 * i32;
    Nb[2] = fmaf(r3, t2, s3);
    Nb[3] = l1 * t2;

    Db[0] = -t0;            // unscaled: true deriv = 3*29*D, cancels later
    Db[1] = t0 - t1;
    Db[2] = t1 - t2;
    Db[3] = t2;
}

extern "C" __global__ void __launch_bounds__(NTHREADS, 1)
nurbs_surface_kernel(const float2* __restrict__ ep,
                     const float*  __restrict__ cp,
                     float4* __restrict__ out,
                     int n)
{
    extern __shared__ float4 tab[];   // [1024 cells][8 bank-columns]
    const int tid   = threadIdx.x;
    const int lane8 = tid & 7;

#pragma unroll
    for (int i = 0; i < 8; ++i) {
        int e = i * NTHREADS + tid;
        int cell = e >> 3;
        tab[e] = make_float4(cp[3 * cell + 0], cp[3 * cell + 1], cp[3 * cell + 2], 1.0f);
    }
    __syncthreads();

    const int stride = NBLOCKS * NTHREADS;
    int idx = blockIdx.x * NTHREADS + tid;

    const float2* __restrict__ epp  = ep + idx;
    float4*       __restrict__ outp = out + idx;
    float4*       __restrict__ outq = out + n + idx;

    for (; idx < n; idx += stride, epp += stride, outp += stride, outq += stride) {
        float2 uv = *epp;

        // u,v in [0,1) -> u*29 in [0,29) -> trunc-cast alone gives [0,28]
        int se = (int)(uv.x * 29.0f);
        int sn = (int)(uv.y * 29.0f);

        float Nu[4], Du[4], Nv[4], Dv[4];
        basis3(uv.x, se, Nu, Du);
        basis3(uv.y, sn, Nv, Dv);

        // Conflict-free gather base: this lane's private bank column.
        const float4* __restrict__ p = tab + ((se * NCP + sn) * 8 + lane8);

        float px=0.f,py=0.f,pz=0.f;   // surface point (homogeneous w == 1)
        float ex=0.f,ey=0.f,ez=0.f;   // ~ d/du
        float fx=0.f,fy=0.f,fz=0.f;   // ~ d/dv
#pragma unroll
        for (int r = 0; r < 4; ++r) {
            float ax=0.f, ay=0.f, az=0.f;
            float bx=0.f, by=0.f, bz=0.f;
#pragma unroll
            for (int s = 0; s < 4; ++s) {
                float4 g = p[(r * NCP + s) * 8];
                float nv = Nv[s], dv = Dv[s];
                ax = fmaf(nv, g.x, ax); ay = fmaf(nv, g.y, ay); az = fmaf(nv, g.z, az);
                bx = fmaf(dv, g.x, bx); by = fmaf(dv, g.y, by); bz = fmaf(dv, g.z, bz);
            }
            float nu = Nu[r], du = Du[r];
            px = fmaf(nu, ax, px); py = fmaf(nu, ay, py); pz = fmaf(nu, az, pz);
            ex = fmaf(du, ax, ex); ey = fmaf(du, ay, ey); ez = fmaf(du, az, ez);
            fx = fmaf(nu, bx, fx); fy = fmaf(nu, by, fy); fz = fmaf(nu, bz, fz);
        }

        // normal = normalize(cross(d_e, d_n)); uniform scales cancel
        float cx = ey * fz - ez * fy;
        float cy = ez * fx - ex * fz;
        float cz = ex * fy - ey * fx;
        float il = rsqrtf(cx * cx + cy * cy + cz * cz);

        *outp = make_float4(px, py, pz, 1.0f);
        *outq = make_float4(cx * il, cy * il, cz * il, 0.0f);
    }
}

extern "C" void kernel_launch(void* const* d_in, const int* in_sizes, int n_in,
                              void* d_out, int out_size)
{
    const float2* ep = (const float2*)d_in[0];   // evaluation_points (N,2)
    const float*  cp = (const float*)d_in[1];    // control_points (32,32,3)
    int n = in_sizes[0] / 2;
    float4* out = (float4*)d_out;

    cudaFuncSetAttribute(nurbs_surface_kernel,
                         cudaFuncAttributeMaxDynamicSharedMemorySize, TAB_BYTES);

    nurbs_surface_kernel<<<NBLOCKS, NTHREADS, TAB_BYTES>>>(ep, cp, out, n);
}